// round 17
// baseline (speedup 1.0000x reference)
#include <cuda_runtime.h>
#include <cuda_fp16.h>

#define NND 2048
#define NF  32
#define NC  3
#define NH  35
#define H1  64
#define H2  32

// ---------------- scratch (device globals, no allocs) ----------------
__device__ __align__(16) float g_invn[NND];
__device__ __align__(16) float g_s[NND * NF];          // x^2 * invnorm
__device__ __align__(16) float g_partA[128 * NF];      // chunk sums of g_s (16-row chunks)
__device__ __align__(16) float g_credp[16 * NND * 3];  // per-i-tile centroid partials
__device__ __align__(16) float g_h1[NND * H1];
__device__ __align__(16) float g_partB[128 * H1];      // chunk sums of h1 (16-row chunks)
__device__ __align__(16) float g_A[NND * H2];          // h2 @ Wm1[0:32] + bm1
__device__ __align__(16) float g_B[NND * H2];          // h2 @ Wm1[32:64]
__device__ __align__(16) float g_wd[H2];
__device__ float g_bd;

// ================ K1: norm/partials (blocks 0..127) + centroid tiles (128..263) ================
__global__ void __launch_bounds__(512) k_pre(const float* __restrict__ x,
                                             const float* __restrict__ cent) {
    int blk = blockIdx.x;
    int t = threadIdx.x;
    if (blk < 128) {
        int f = t & 31, r = t >> 5;
        int node = blk * 16 + r;
        float v = x[node * NF + f];
        float sq = v * v;
        float sum = sq;
#pragma unroll
        for (int m = 16; m > 0; m >>= 1) sum += __shfl_xor_sync(0xffffffffu, sum, m);
        float invn = rsqrtf(sum);
        if (f == 0) g_invn[node] = invn;
        float s = sq * invn;
        g_s[node * NF + f] = s;
        __shared__ float sm[16][33];
        sm[r][f] = s;
        __syncthreads();
        if (r < 8) sm[r][f] += sm[r + 8][f];
        __syncthreads();
        if (r < 4) sm[r][f] += sm[r + 4][f];
        __syncthreads();
        if (r < 2) sm[r][f] += sm[r + 2][f];
        __syncthreads();
        if (r == 0) g_partA[blk * NF + f] = sm[0][f] + sm[1][f];
    } else {
        if (t >= 128) return;
        int rr = blk - 128;
        int bj = 0;
        while (rr >= bj + 1) { rr -= bj + 1; bj++; }
        int bi = rr;  // bi <= bj
        __shared__ float sc[3][128];
        int i0 = bi * 128;
        sc[0][t] = cent[(i0 + t) * 3 + 0];
        sc[1][t] = cent[(i0 + t) * 3 + 1];
        sc[2][t] = cent[(i0 + t) * 3 + 2];
        __syncthreads();
        int j = bj * 128 + t;
        float cj0 = cent[j * 3 + 0], cj1 = cent[j * 3 + 1], cj2 = cent[j * 3 + 2];
        int lim = j - i0;
        if (lim > 128) lim = 128;
        float t0 = 0.f, t1 = 0.f, t2 = 0.f;
#pragma unroll 4
        for (int il = 0; il < lim; il++) {
            float a = sc[0][il], b = sc[1][il], c = sc[2][il];
            t0 += a * fabsf(a - cj0);
            t1 += b * fabsf(b - cj1);
            t2 += c * fabsf(c - cj2);
        }
        size_t o = ((size_t)bi * NND + j) * 3;
        g_credp[o + 0] = t0;
        g_credp[o + 1] = t1;
        g_credp[o + 2] = t2;
    }
}

// ================ K2: h1 GEMM with fused scan-A offset + cred sums + partB ================
// grid 128, block 512, 16 nodes/block
__global__ void __launch_bounds__(512) k_h1f(const float* __restrict__ x,
                                             const float* __restrict__ cent,
                                             const float* __restrict__ Ws1,
                                             const float* __restrict__ Wn1,
                                             const float* __restrict__ b1) {
    __shared__ float sWs[NH][H1];
    __shared__ float sWn[NH][H1];
    __shared__ float sg[16][33];
    __shared__ float sredA[8][NF];
    __shared__ float soff[NF];
    __shared__ float scred[16][3];
    __shared__ float sH[16][36];
    __shared__ float sN[16][36];
    __shared__ float sRed[16][H1 + 1];

    int t = threadIdx.x;
    int blk = blockIdx.x;
    int nbase = blk * 16;

    for (int idx = t; idx < NH * H1; idx += 512) {
        sWs[idx / H1][idx % H1] = Ws1[idx];
        sWn[idx / H1][idx % H1] = Wn1[idx];
    }
    {
        int f = t & 31, n = t >> 5;
        if (n < 16) sg[n][f] = g_s[(nbase + n) * NF + f];
    }
    if (t >= 128 && t < 384) {
        int f = (t - 128) & 31, q = (t - 128) >> 5;
        float a0 = 0.f, a1 = 0.f;
        for (int c = q; c < blk; c += 16) {
            a0 += g_partA[c * NF + f];
            int c2 = c + 8;
            if (c2 < blk) a1 += g_partA[c2 * NF + f];
        }
        sredA[q][f] = a0 + a1;
    }
    if (t >= 64 && t < 64 + 48) {
        int nd = t - 64;
        int n = nd / 3, d = nd % 3;
        int node = nbase + n;
        int nt = (node + 127) >> 7;
        float a0 = 0.f, a1 = 0.f, a2 = 0.f, a3 = 0.f;
        int ti = 0;
        for (; ti + 4 <= nt; ti += 4) {
            a0 += g_credp[((size_t)(ti + 0) * NND + node) * 3 + d];
            a1 += g_credp[((size_t)(ti + 1) * NND + node) * 3 + d];
            a2 += g_credp[((size_t)(ti + 2) * NND + node) * 3 + d];
            a3 += g_credp[((size_t)(ti + 3) * NND + node) * 3 + d];
        }
        for (; ti < nt; ti++) a0 += g_credp[((size_t)ti * NND + node) * 3 + d];
        scred[n][d] = (a0 + a1) + (a2 + a3);
    }
    __syncthreads();
    if (t < 32) {
        float s = 0.f;
#pragma unroll
        for (int q = 0; q < 8; q++) s += sredA[q][t];
        soff[t] = s;
    }
    __syncthreads();

    for (int idx = t; idx < 16 * NH; idx += 512) {
        int n = idx / NH, c = idx % NH;
        int node = nbase + n;
        float invdeg = (node > 0) ? (1.f / (float)node) : 0.f;
        float hv, nv;
        if (c < NF) {
            hv = x[node * NF + c];
            float S = soff[c];
            for (int r = 0; r < n; r++) S += sg[r][c];
            nv = invdeg * hv * g_invn[node] * S;
        } else {
            int d = c - NF;
            hv = cent[node * NC + d];
            nv = invdeg * scred[n][d];
        }
        sH[n][c] = hv;
        sN[n][c] = nv;
    }
    __syncthreads();

    int f = t & 63, g = t >> 6;  // g in 0..7 -> nodes g and g+8
    float acc0 = b1[f], acc1 = acc0;
#pragma unroll
    for (int c = 0; c < NH; c++) {
        float ws = sWs[c][f], wn = sWn[c][f];
        acc0 += sH[g][c] * ws + sN[g][c] * wn;
        acc1 += sH[g + 8][c] * ws + sN[g + 8][c] * wn;
    }
    g_h1[(nbase + g) * H1 + f] = acc0;
    g_h1[(nbase + g + 8) * H1 + f] = acc1;

    sRed[g][f] = acc0 + acc1;
    __syncthreads();
    if (g < 4) sRed[g][f] += sRed[g + 4][f];
    __syncthreads();
    if (g < 2) sRed[g][f] += sRed[g + 2][f];
    __syncthreads();
    if (g == 0) g_partB[blk * H1 + f] = sRed[0][f] + sRed[1][f];
}

// ================ K3: h2 + A/B with fused scan-B prefix ================
// grid 256, block 256, 8 nodes/block
__global__ void __launch_bounds__(256) k_h2AB(const float* __restrict__ b2,
                                              const float* __restrict__ Ws2,
                                              const float* __restrict__ Wn2,
                                              const float* __restrict__ Wm1,
                                              const float* __restrict__ bm1,
                                              const float* __restrict__ Wm2,
                                              const float* __restrict__ bm2) {
    __shared__ float sWs2[H1][H2];
    __shared__ float sWn2[H1][H2];
    __shared__ float sWm1[H1][H2];
    __shared__ float sHx[16][H1 + 1];
    __shared__ float sP1[8][H1 + 1];
    __shared__ float h2s[8][H2 + 1];
    __shared__ float soffB[H1];
    __shared__ float red[4][H1];

    int t = threadIdx.x;
    int blk = blockIdx.x;
    int nbase = blk * 8;
    int chunkbase = nbase & ~15;
    int own0 = nbase - chunkbase;  // 0 or 8

    for (int idx = t; idx < H1 * H2; idx += 256) {
        sWs2[idx / H2][idx % H2] = Ws2[idx];
        sWn2[idx / H2][idx % H2] = Wn2[idx];
        sWm1[idx / H2][idx % H2] = Wm1[idx];
    }
    for (int idx = t; idx < 16 * H1; idx += 256) {
        int r = idx >> 6, c = idx & 63;
        sHx[r][c] = g_h1[(chunkbase + r) * H1 + c];
    }
    {
        int grp = t >> 6, c = t & 63;
        int CB = blk >> 1;
        float a[8];
#pragma unroll
        for (int q = 0; q < 8; q++) a[q] = 0.f;
        for (int base = grp; base < CB; base += 32) {
#pragma unroll
            for (int q = 0; q < 8; q++) {
                int cc = base + 4 * q;
                if (cc < CB) a[q] += g_partB[cc * H1 + c];
            }
        }
        red[grp][c] = ((a[0] + a[1]) + (a[2] + a[3])) + ((a[4] + a[5]) + (a[6] + a[7]));
    }
    __syncthreads();
    if (t < 64) soffB[t] = ((red[0][t] + red[1][t]) + (red[2][t] + red[3][t]));
    __syncthreads();
    for (int e = t; e < 8 * H1; e += 256) {
        int n = e >> 6, c = e & 63;
        int node = nbase + n;
        int L = node - chunkbase;
        float s = soffB[c];
        for (int r = 0; r < L; r++) s += sHx[r][c];
        float invdeg = (node > 0) ? (1.f / (float)node) : 0.f;
        sP1[n][c] = s * invdeg;
    }
    __syncthreads();

    int ty = t >> 5, f = t & 31;
    float acc = b2[f];
#pragma unroll 8
    for (int c = 0; c < H1; c++) {
        acc += sHx[own0 + ty][c] * sWs2[c][f] + sP1[ty][c] * sWn2[c][f];
    }
    h2s[ty][f] = acc;
    __syncthreads();
    float accA = bm1[f], accB = 0.f;
#pragma unroll
    for (int c = 0; c < H2; c++) {
        float v = h2s[ty][c];
        accA += v * sWm1[c][f];
        accB += v * sWm1[H2 + c][f];
    }
    int node = nbase + ty;
    g_A[node * H2 + f] = accA;
    g_B[node * H2 + f] = accB;
    if (blk == 0 && ty == 0) {
        g_wd[f] = Wm2[f * 2 + 0] - Wm2[f * 2 + 1];
        if (f == 0) g_bd = bm2[0] - bm2[1];
    }
}

// ================ K4: edge kernel — f16x2, 64(i)x32(j) tiles, 128 thr, 8 blocks/SM ==========
// Triangular grid over (bi: 32 i-tiles of 64) x (bj: 64 j-tiles of 32), keep bj >= 2*bi.
// count per bi = 64 - 2*bi -> total 1056 blocks.
#define TI 64
#define TJ 32
__global__ void __launch_bounds__(128, 8) k_edge(float* __restrict__ out) {
    int r0 = blockIdx.x;
    int bi = 0;
    while (r0 >= 64 - 2 * bi) { r0 -= 64 - 2 * bi; bi++; }
    int bj = 2 * bi + r0;
    int i0 = bi * TI, j0 = bj * TJ;

    __shared__ unsigned sAh[16][68];   // k2-major: 16 k-pairs x 64 i half2 (+pad, 16B-aligned rows)
    __shared__ unsigned sBh[16][36];   // 16 k-pairs x 32 j half2 (+pad)
    __shared__ unsigned swh[16];       // half2 wd pairs
    __shared__ float sbd;

    int t = threadIdx.x;  // 128
    {
        const float4* gA4 = (const float4*)(g_A + (size_t)i0 * H2);
#pragma unroll
        for (int u = 0; u < 4; u++) {  // 512 float4 of A
            int v = t + u * 128;
            int r = v >> 3, q = v & 7;
            float4 qa = gA4[v];
            __half2 h0 = __floats2half2_rn(qa.x, qa.y);
            __half2 h1v = __floats2half2_rn(qa.z, qa.w);
            sAh[2 * q + 0][r] = *(unsigned*)&h0;
            sAh[2 * q + 1][r] = *(unsigned*)&h1v;
        }
        const float4* gB4 = (const float4*)(g_B + (size_t)j0 * H2);
#pragma unroll
        for (int u = 0; u < 2; u++) {  // 256 float4 of B
            int v = t + u * 128;
            int r = v >> 3, q = v & 7;
            float4 qb = gB4[v];
            __half2 h0 = __floats2half2_rn(qb.x, qb.y);
            __half2 h1v = __floats2half2_rn(qb.z, qb.w);
            sBh[2 * q + 0][r] = *(unsigned*)&h0;
            sBh[2 * q + 1][r] = *(unsigned*)&h1v;
        }
        if (t < 16) {
            __half2 hw = __floats2half2_rn(g_wd[2 * t], g_wd[2 * t + 1]);
            swh[t] = *(unsigned*)&hw;
        }
        if (t == 0) sbd = g_bd;
    }
    __syncthreads();

    int tx = t & 7, ty = t >> 3;   // ty: 16 i-groups of 4; tx: 8 j-groups of 4
    __half2 acc[4][4];
    const __half2 hzero = __float2half2_rn(0.f);
#pragma unroll
    for (int a = 0; a < 4; a++)
#pragma unroll
        for (int b = 0; b < 4; b++) acc[a][b] = hzero;

#pragma unroll
    for (int k2 = 0; k2 < 16; k2++) {
        unsigned wu = swh[k2];
        __half2 w2 = *(__half2*)&wu;
        uint4 au = *(const uint4*)&sAh[k2][ty * 4];   // 4 i half2 (16B aligned: row 272B, off 16B)
        uint4 bu = *(const uint4*)&sBh[k2][tx * 4];   // 4 j half2 (row 144B, off 16B)
        __half2 av[4] = {*(__half2*)&au.x, *(__half2*)&au.y, *(__half2*)&au.z, *(__half2*)&au.w};
        __half2 bv[4] = {*(__half2*)&bu.x, *(__half2*)&bu.y, *(__half2*)&bu.z, *(__half2*)&bu.w};
#pragma unroll
        for (int a = 0; a < 4; a++)
#pragma unroll
            for (int b = 0; b < 4; b++) {
                __half2 s = __hmax2(__hadd2(av[a], bv[b]), hzero);
                acc[a][b] = __hfma2(s, w2, acc[a][b]);
            }
    }

    float bd = sbd;
#pragma unroll
    for (int a = 0; a < 4; a++) {
        int i = i0 + ty * 4 + a;
        int basei = i * (2 * NND - 1 - i) / 2 - i - 1;  // e = basei + j
        int jlo = j0 + tx * 4;
#pragma unroll
        for (int b = 0; b < 4; b++) {
            int j = jlo + b;
            if (j > i) {
                float2 lh = __half22float2(acc[a][b]);
                float d  = lh.x + lh.y + bd;  // z0 - z1
                float ex = __expf(-d);
                float p0 = __fdividef(1.f, 1.f + ex);
                float p1 = 1.f - p0;
                ((float2*)out)[basei + j] = make_float2(p0, p1);
            }
        }
    }
}

// ---------------- launch ----------------
extern "C" void kernel_launch(void* const* d_in, const int* in_sizes, int n_in,
                              void* d_out, int out_size) {
    const float* x    = (const float*)d_in[0];
    const float* cent = (const float*)d_in[1];
    const float* Ws1  = (const float*)d_in[2];
    const float* Wn1  = (const float*)d_in[3];
    const float* b1   = (const float*)d_in[4];
    const float* Ws2  = (const float*)d_in[5];
    const float* Wn2  = (const float*)d_in[6];
    const float* b2   = (const float*)d_in[7];
    const float* Wm1  = (const float*)d_in[8];
    const float* bm1  = (const float*)d_in[9];
    const float* Wm2  = (const float*)d_in[10];
    const float* bm2  = (const float*)d_in[11];
    float* out = (float*)d_out;

    k_pre<<<128 + 136, 512>>>(x, cent);
    k_h1f<<<128, 512>>>(x, cent, Ws1, Wn1, b1);
    k_h2AB<<<256, 256>>>(b2, Ws2, Wn2, Wm1, bm1, Wm2, bm2);
    k_edge<<<1056, 128>>>(out);
}